// round 14
// baseline (speedup 1.0000x reference)
#include <cuda_runtime.h>
#include <cuda_fp16.h>
#include <stdint.h>

#define N_NODES 50000
#define N_EDGES 50000
#define IN_C 256
#define HID_C 128
#define OUT_C 64
#define MAX_NNZ 800000

// ---------------- scratch (no allocations allowed) ----------------
__device__ __half g_h0h[(size_t)N_NODES * HID_C];  // x @ W1 (fp16)
__device__ __half g_h1h[(size_t)N_NODES * OUT_C];  // f1 @ W2 (fp16)
__device__ __half g_mh [(size_t)N_EDGES * HID_C];  // edge buffer (fp16, reused at C=64)
__device__ float g_dinv[N_NODES];
__device__ float g_binv[N_EDGES];

__device__ int g_cnt[4 * N_EDGES];   // [ecnt | ncnt | ecur | ncur]
__device__ int g_eoff[N_EDGES + 1];
__device__ int g_noff[N_NODES + 1];
__device__ int g_eadj[MAX_NNZ];
__device__ int g_nadj[MAX_NNZ];

// ---------------- histogram ----------------
__global__ void hist_kernel(const int* __restrict__ node_idx,
                            const int* __restrict__ edge_idx,
                            int* __restrict__ ncnt, int* __restrict__ ecnt, int nnz) {
    int t = blockIdx.x * blockDim.x + threadIdx.x;
    if (t < nnz) {
        atomicAdd(&ncnt[node_idx[t]], 1);
        atomicAdd(&ecnt[edge_idx[t]], 1);
    }
}

// ---------------- exclusive scan + fused 1/count ----------------
__global__ void scan_kernel(const int* __restrict__ cntE, int* __restrict__ offE,
                            const int* __restrict__ cntN, int* __restrict__ offN,
                            float* __restrict__ binv, float* __restrict__ dinv, int n) {
    const int* cnt = (blockIdx.x == 0) ? cntE : cntN;
    int* off       = (blockIdx.x == 0) ? offE : offN;
    float* inv     = (blockIdx.x == 0) ? binv : dinv;
    __shared__ int sh[1024];
    int tid = threadIdx.x;
    int chunk = (n + 1023) / 1024;
    int start = tid * chunk;
    int end = min(start + chunk, n);
    int s = 0;
    for (int i = start; i < end; i++) {
        int c = cnt[i];
        s += c;
        inv[i] = (c > 0) ? (1.0f / (float)c) : 0.0f;
    }
    sh[tid] = s;
    __syncthreads();
    for (int d = 1; d < 1024; d <<= 1) {
        int v = (tid >= d) ? sh[tid - d] : 0;
        __syncthreads();
        sh[tid] += v;
        __syncthreads();
    }
    int run = (tid == 0) ? 0 : sh[tid - 1];
    for (int i = start; i < end; i++) {
        off[i] = run;
        run += cnt[i];
    }
    if (tid == 1023) off[n] = sh[1023];
}

// ---------------- CSR fill ----------------
__global__ void fill_kernel(const int* __restrict__ node_idx, const int* __restrict__ edge_idx,
                            const int* __restrict__ eoff, const int* __restrict__ noff,
                            int* __restrict__ ecur, int* __restrict__ ncur,
                            int* __restrict__ eadj, int* __restrict__ nadj, int nnz) {
    int t = blockIdx.x * blockDim.x + threadIdx.x;
    if (t < nnz) {
        int nd = node_idx[t];
        int eg = edge_idx[t];
        int p = atomicAdd(&ecur[eg], 1);
        eadj[eoff[eg] + p] = nd;
        int q = atomicAdd(&ncur[nd], 1);
        nadj[noff[nd] + q] = eg;
    }
}

// ---------------- pass1: fp16 gather -> fp32 accum -> fp16 out (edge rows) ----------------
template <int VEC>
__global__ void agg_p1(const __half* __restrict__ src, const int* __restrict__ adj,
                       const int* __restrict__ off, __half* __restrict__ out, int rows) {
    int warp = (blockIdx.x * blockDim.x + threadIdx.x) >> 5;
    int lane = threadIdx.x & 31;
    if (warp >= rows) return;
    const int C = 32 * VEC;
    int s0 = off[warp];
    int s1 = off[warp + 1];
    int lo = lane * VEC;

    float acc[VEC];
#pragma unroll
    for (int k = 0; k < VEC; k++) acc[k] = 0.0f;

    int j = s0;
    for (; j + 4 <= s1; j += 4) {
        int nb0 = adj[j + 0], nb1 = adj[j + 1], nb2 = adj[j + 2], nb3 = adj[j + 3];
        const __half2* p0 = reinterpret_cast<const __half2*>(src + (size_t)nb0 * C + lo);
        const __half2* p1 = reinterpret_cast<const __half2*>(src + (size_t)nb1 * C + lo);
        const __half2* p2 = reinterpret_cast<const __half2*>(src + (size_t)nb2 * C + lo);
        const __half2* p3 = reinterpret_cast<const __half2*>(src + (size_t)nb3 * C + lo);
#pragma unroll
        for (int h = 0; h < VEC / 2; h++) {
            float2 a = __half22float2(p0[h]);
            float2 b = __half22float2(p1[h]);
            float2 c = __half22float2(p2[h]);
            float2 d = __half22float2(p3[h]);
            acc[2 * h + 0] += a.x + b.x + c.x + d.x;
            acc[2 * h + 1] += a.y + b.y + c.y + d.y;
        }
    }
    for (; j < s1; j++) {
        int nb = adj[j];
        const __half2* p = reinterpret_cast<const __half2*>(src + (size_t)nb * C + lo);
#pragma unroll
        for (int h = 0; h < VEC / 2; h++) {
            float2 a = __half22float2(p[h]);
            acc[2 * h + 0] += a.x;
            acc[2 * h + 1] += a.y;
        }
    }

    __half2* q = reinterpret_cast<__half2*>(out + (size_t)warp * C + lo);
#pragma unroll
    for (int h = 0; h < VEC / 2; h++)
        q[h] = __floats2half2_rn(acc[2 * h + 0], acc[2 * h + 1]);
}

// ---------------- pass2: fp16 gather (scaled) -> fp32 final with dinv/bias/relu ----------------
template <int VEC>
__global__ void agg_p2(const __half* __restrict__ src, const int* __restrict__ adj,
                       const int* __restrict__ off, const float* __restrict__ sscale,
                       float* __restrict__ out, const float* __restrict__ rscale,
                       const float* __restrict__ bias, int rows) {
    int warp = (blockIdx.x * blockDim.x + threadIdx.x) >> 5;
    int lane = threadIdx.x & 31;
    if (warp >= rows) return;
    const int C = 32 * VEC;
    int s0 = off[warp];
    int s1 = off[warp + 1];
    int lo = lane * VEC;

    float acc[VEC];
#pragma unroll
    for (int k = 0; k < VEC; k++) acc[k] = 0.0f;

    int j = s0;
    for (; j + 4 <= s1; j += 4) {
        int nb0 = adj[j + 0], nb1 = adj[j + 1], nb2 = adj[j + 2], nb3 = adj[j + 3];
        float c0 = sscale[nb0], c1 = sscale[nb1], c2 = sscale[nb2], c3 = sscale[nb3];
        const __half2* p0 = reinterpret_cast<const __half2*>(src + (size_t)nb0 * C + lo);
        const __half2* p1 = reinterpret_cast<const __half2*>(src + (size_t)nb1 * C + lo);
        const __half2* p2 = reinterpret_cast<const __half2*>(src + (size_t)nb2 * C + lo);
        const __half2* p3 = reinterpret_cast<const __half2*>(src + (size_t)nb3 * C + lo);
#pragma unroll
        for (int h = 0; h < VEC / 2; h++) {
            float2 a = __half22float2(p0[h]);
            float2 b = __half22float2(p1[h]);
            float2 c = __half22float2(p2[h]);
            float2 d = __half22float2(p3[h]);
            acc[2 * h + 0] += a.x * c0 + b.x * c1 + c.x * c2 + d.x * c3;
            acc[2 * h + 1] += a.y * c0 + b.y * c1 + c.y * c2 + d.y * c3;
        }
    }
    for (; j < s1; j++) {
        int nb = adj[j];
        float sc = sscale[nb];
        const __half2* p = reinterpret_cast<const __half2*>(src + (size_t)nb * C + lo);
#pragma unroll
        for (int h = 0; h < VEC / 2; h++) {
            float2 a = __half22float2(p[h]);
            acc[2 * h + 0] += a.x * sc;
            acc[2 * h + 1] += a.y * sc;
        }
    }

    float rs = rscale[warp];
#pragma unroll
    for (int k = 0; k < VEC; k++)
        acc[k] = fmaxf(acc[k] * rs + bias[lo + k], 0.0f);

    float* q = out + (size_t)warp * C + lo;
    if (VEC == 4) {
        *reinterpret_cast<float4*>(q) = make_float4(acc[0], acc[1], acc[2], acc[3]);
    } else {
        *reinterpret_cast<float2*>(q) = make_float2(acc[0], acc[1]);
    }
}

// ---------------- 2xTF32 tensor-core GEMM (A split hi+lo, B single tf32) ----------------
__device__ __forceinline__ uint32_t f2tf32(float x) {
    uint32_t r;
    asm("cvt.rna.tf32.f32 %0, %1;" : "=r"(r) : "f"(x));
    return r;
}

__device__ __forceinline__ void mma_tf32(float* c, const uint32_t* a, const uint32_t* b) {
    asm("mma.sync.aligned.m16n8k8.row.col.f32.tf32.tf32.f32 "
        "{%0,%1,%2,%3}, {%4,%5,%6,%7}, {%8,%9}, {%0,%1,%2,%3};"
        : "+f"(c[0]), "+f"(c[1]), "+f"(c[2]), "+f"(c[3])
        : "r"(a[0]), "r"(a[1]), "r"(a[2]), "r"(a[3]), "r"(b[0]), "r"(b[1]));
}

// C[M,N] = A[M,K] @ B[K,N] (+bias fp32 path). BM=128, BN=64, BK=32, 256 threads.
template <bool HALF_OUT>
__global__ void __launch_bounds__(256)
tf32_gemm(const float* __restrict__ A, const float* __restrict__ B,
          void* __restrict__ Cv, int M, int N, int K,
          const float* __restrict__ bias) {
    const int BM = 128, BN = 64, BK = 32;
    const int AS = BK + 4;
    __shared__ uint32_t Ahi[BM][AS];
    __shared__ uint32_t Alo[BM][AS];
    __shared__ uint32_t Bs [BK][BN + 8];

    int tid = threadIdx.x;
    int wid = tid >> 5;
    int lane = tid & 31;
    int gid = lane >> 2;
    int tg = lane & 3;
    int warp_m = wid >> 1;
    int warp_n = wid & 1;
    int mb = warp_m * 32;
    int nb = warp_n * 32;

    int rowBase = blockIdx.x * BM;
    int colBase = blockIdx.y * BN;

    float acc[2][4][4];
#pragma unroll
    for (int t = 0; t < 2; t++)
#pragma unroll
        for (int u = 0; u < 4; u++)
#pragma unroll
            for (int k = 0; k < 4; k++) acc[t][u][k] = 0.0f;

    for (int k0 = 0; k0 < K; k0 += BK) {
#pragma unroll
        for (int it = 0; it < 4; it++) {
            int idx = tid * 4 + it * 1024;
            int r = idx / BK;
            int c = idx % BK;
            int gr = rowBase + r;
            float4 v = make_float4(0.f, 0.f, 0.f, 0.f);
            if (gr < M)
                v = *reinterpret_cast<const float4*>(A + (size_t)gr * K + k0 + c);
            uint4 hi, lo;
            hi.x = f2tf32(v.x); lo.x = f2tf32(v.x - __uint_as_float(hi.x));
            hi.y = f2tf32(v.y); lo.y = f2tf32(v.y - __uint_as_float(hi.y));
            hi.z = f2tf32(v.z); lo.z = f2tf32(v.z - __uint_as_float(hi.z));
            hi.w = f2tf32(v.w); lo.w = f2tf32(v.w - __uint_as_float(hi.w));
            *reinterpret_cast<uint4*>(&Ahi[r][c]) = hi;
            *reinterpret_cast<uint4*>(&Alo[r][c]) = lo;
        }
#pragma unroll
        for (int it = 0; it < 2; it++) {
            int idx = tid * 4 + it * 1024;
            int r = idx / BN;
            int c = idx % BN;
            float4 v = *reinterpret_cast<const float4*>(B + (size_t)(k0 + r) * N + colBase + c);
            Bs[r][c + 0] = f2tf32(v.x);
            Bs[r][c + 1] = f2tf32(v.y);
            Bs[r][c + 2] = f2tf32(v.z);
            Bs[r][c + 3] = f2tf32(v.w);
        }
        __syncthreads();

#pragma unroll
        for (int ks = 0; ks < 4; ks++) {
            int k = ks * 8;
            uint32_t ahi[2][4], alo[2][4];
#pragma unroll
            for (int t = 0; t < 2; t++) {
                int m = mb + t * 16 + gid;
                ahi[t][0] = Ahi[m][k + tg];
                ahi[t][1] = Ahi[m + 8][k + tg];
                ahi[t][2] = Ahi[m][k + tg + 4];
                ahi[t][3] = Ahi[m + 8][k + tg + 4];
                alo[t][0] = Alo[m][k + tg];
                alo[t][1] = Alo[m + 8][k + tg];
                alo[t][2] = Alo[m][k + tg + 4];
                alo[t][3] = Alo[m + 8][k + tg + 4];
            }
            uint32_t bf[4][2];
#pragma unroll
            for (int u = 0; u < 4; u++) {
                int n = nb + u * 8 + gid;
                bf[u][0] = Bs[k + tg][n];
                bf[u][1] = Bs[k + tg + 4][n];
            }
#pragma unroll
            for (int t = 0; t < 2; t++)
#pragma unroll
                for (int u = 0; u < 4; u++) {
                    mma_tf32(acc[t][u], ahi[t], bf[u]);
                    mma_tf32(acc[t][u], alo[t], bf[u]);
                }
        }
        __syncthreads();
    }

#pragma unroll
    for (int t = 0; t < 2; t++) {
#pragma unroll
        for (int u = 0; u < 4; u++) {
            int row = rowBase + mb + t * 16 + gid;
            int col = colBase + nb + u * 8 + tg * 2;
            if (HALF_OUT) {
                __half* C = (__half*)Cv;
                if (row < M)
                    *reinterpret_cast<__half2*>(C + (size_t)row * N + col) =
                        __floats2half2_rn(acc[t][u][0], acc[t][u][1]);
                if (row + 8 < M)
                    *reinterpret_cast<__half2*>(C + (size_t)(row + 8) * N + col) =
                        __floats2half2_rn(acc[t][u][2], acc[t][u][3]);
            } else {
                float* C = (float*)Cv;
                float b0 = 0.f, b1 = 0.f;
                if (bias) { b0 = bias[col]; b1 = bias[col + 1]; }
                if (row < M) {
                    float2 v = make_float2(acc[t][u][0] + b0, acc[t][u][1] + b1);
                    *reinterpret_cast<float2*>(C + (size_t)row * N + col) = v;
                }
                if (row + 8 < M) {
                    float2 v = make_float2(acc[t][u][2] + b0, acc[t][u][3] + b1);
                    *reinterpret_cast<float2*>(C + (size_t)(row + 8) * N + col) = v;
                }
            }
        }
    }
}

// ---------------- launch ----------------
extern "C" void kernel_launch(void* const* d_in, const int* in_sizes, int n_in,
                              void* d_out, int out_size) {
    const float* x    = (const float*)d_in[0];
    const int*   hidx = (const int*)d_in[1];   // int32 on device (JAX x64 disabled)
    const float* W1   = (const float*)d_in[2];
    const float* b1   = (const float*)d_in[3];
    const float* W2   = (const float*)d_in[4];
    const float* b2   = (const float*)d_in[5];
    const float* Wp   = (const float*)d_in[6];
    const float* bp   = (const float*)d_in[7];

    int nnz = in_sizes[1] / 2;
    const int* node_idx = hidx;
    const int* edge_idx = hidx + nnz;

    // output layout: (z [N,64], features_1 [N,128], features_2 [N,64])
    float* z  = (float*)d_out;
    float* f1 = z  + (size_t)N_NODES * OUT_C;
    float* f2 = f1 + (size_t)N_NODES * HID_C;

    __half *p_h0h, *p_h1h, *p_mh;
    float *p_dinv, *p_binv;
    int *p_cnt, *p_eoff, *p_noff, *p_eadj, *p_nadj;
    cudaGetSymbolAddress((void**)&p_h0h,  g_h0h);
    cudaGetSymbolAddress((void**)&p_h1h,  g_h1h);
    cudaGetSymbolAddress((void**)&p_mh,   g_mh);
    cudaGetSymbolAddress((void**)&p_dinv, g_dinv);
    cudaGetSymbolAddress((void**)&p_binv, g_binv);
    cudaGetSymbolAddress((void**)&p_cnt,  g_cnt);
    cudaGetSymbolAddress((void**)&p_eoff, g_eoff);
    cudaGetSymbolAddress((void**)&p_noff, g_noff);
    cudaGetSymbolAddress((void**)&p_eadj, g_eadj);
    cudaGetSymbolAddress((void**)&p_nadj, g_nadj);

    int* p_ecnt = p_cnt;
    int* p_ncnt = p_cnt + N_EDGES;
    int* p_ecur = p_cnt + 2 * N_EDGES;
    int* p_ncur = p_cnt + 3 * N_EDGES;

    // lazily-created side stream + events (host-side infra, created once on the
    // first (correctness) call; graph capture then records the fork/join)
    static cudaStream_t s_csr = nullptr;
    static cudaEvent_t ev_fork = nullptr, ev_join = nullptr;
    if (!s_csr) {
        cudaStreamCreateWithFlags(&s_csr, cudaStreamNonBlocking);
        cudaEventCreateWithFlags(&ev_fork, cudaEventDisableTiming);
        cudaEventCreateWithFlags(&ev_join, cudaEventDisableTiming);
    }

    int agg_blocks = (N_EDGES * 32 + 255) / 256;
    dim3 ggrid((N_NODES + 127) / 128, 1);

    // ---- fork: CSR build on side stream, gemm1 on main stream ----
    cudaEventRecord(ev_fork, 0);
    cudaStreamWaitEvent(s_csr, ev_fork, 0);

    cudaMemsetAsync(p_cnt, 0, 4 * N_EDGES * sizeof(int), s_csr);
    hist_kernel<<<(nnz + 255) / 256, 256, 0, s_csr>>>(node_idx, edge_idx, p_ncnt, p_ecnt, nnz);
    scan_kernel<<<2, 1024, 0, s_csr>>>(p_ecnt, p_eoff, p_ncnt, p_noff, p_binv, p_dinv, N_EDGES);
    fill_kernel<<<(nnz + 255) / 256, 256, 0, s_csr>>>(node_idx, edge_idx, p_eoff, p_noff,
                                                      p_ecur, p_ncur, p_eadj, p_nadj, nnz);
    cudaEventRecord(ev_join, s_csr);

    // ---- layer 1: h0 = x @ W1 (fp16 out) ---- (M=50000, N=128, K=256)
    {
        dim3 grid((N_NODES + 127) / 128, HID_C / 64);
        tf32_gemm<true><<<grid, 256>>>(x, W1, p_h0h, N_NODES, HID_C, IN_C, nullptr);
    }

    // ---- join: aggregation needs both gemm1 and the CSR ----
    cudaStreamWaitEvent(0, ev_join, 0);

    agg_p1<4><<<agg_blocks, 256>>>(p_h0h, p_eadj, p_eoff, p_mh, N_EDGES);
    agg_p2<4><<<agg_blocks, 256>>>(p_mh, p_nadj, p_noff, p_binv, f1, p_dinv, b1, N_NODES);

    // ---- layer 2: h1 = f1 @ W2 (fp16 out) ---- (M=50000, N=64, K=128)
    tf32_gemm<true><<<ggrid, 256>>>(f1, W2, p_h1h, N_NODES, OUT_C, HID_C, nullptr);
    agg_p1<2><<<agg_blocks, 256>>>(p_h1h, p_eadj, p_eoff, p_mh, N_EDGES);
    agg_p2<2><<<agg_blocks, 256>>>(p_mh, p_nadj, p_noff, p_binv, f2, p_dinv, b2, N_NODES);

    // ---- projection: z = f2 @ Wp + bp (fp32 out) ---- (M=50000, N=64, K=64)
    tf32_gemm<false><<<ggrid, 256>>>(f2, Wp, z, N_NODES, OUT_C, OUT_C, bp);
}

// round 15
// speedup vs baseline: 1.1436x; 1.1436x over previous
#include <cuda_runtime.h>
#include <cuda_fp16.h>
#include <stdint.h>

#define N_NODES 50000
#define N_EDGES 50000
#define IN_C 256
#define HID_C 128
#define OUT_C 64
#define MAX_NNZ 800000

// ---------------- scratch (no allocations allowed) ----------------
__device__ __half g_h0h[(size_t)N_NODES * HID_C];  // x @ W1 (fp16)
__device__ __half g_h1h[(size_t)N_NODES * OUT_C];  // f1 @ W2 (fp16)
__device__ __half g_mh [(size_t)N_EDGES * HID_C];  // edge buffer (fp16, reused at C=64)
__device__ float g_dinv[N_NODES];
__device__ float g_binv[N_EDGES];

__device__ int g_cnt[4 * N_EDGES];   // [ecnt | ncnt | ecur | ncur]
__device__ int g_eoff[N_EDGES + 1];
__device__ int g_noff[N_NODES + 1];
__device__ int g_eadj[MAX_NNZ];
__device__ int g_nadj[MAX_NNZ];

// ---------------- histogram ----------------
__global__ void hist_kernel(const int* __restrict__ node_idx,
                            const int* __restrict__ edge_idx,
                            int* __restrict__ ncnt, int* __restrict__ ecnt, int nnz) {
    int t = blockIdx.x * blockDim.x + threadIdx.x;
    if (t < nnz) {
        atomicAdd(&ncnt[node_idx[t]], 1);
        atomicAdd(&ecnt[edge_idx[t]], 1);
    }
}

// ---------------- exclusive scan + fused 1/count ----------------
__global__ void scan_kernel(const int* __restrict__ cntE, int* __restrict__ offE,
                            const int* __restrict__ cntN, int* __restrict__ offN,
                            float* __restrict__ binv, float* __restrict__ dinv, int n) {
    const int* cnt = (blockIdx.x == 0) ? cntE : cntN;
    int* off       = (blockIdx.x == 0) ? offE : offN;
    float* inv     = (blockIdx.x == 0) ? binv : dinv;
    __shared__ int sh[1024];
    int tid = threadIdx.x;
    int chunk = (n + 1023) / 1024;
    int start = tid * chunk;
    int end = min(start + chunk, n);
    int s = 0;
    for (int i = start; i < end; i++) {
        int c = cnt[i];
        s += c;
        inv[i] = (c > 0) ? (1.0f / (float)c) : 0.0f;
    }
    sh[tid] = s;
    __syncthreads();
    for (int d = 1; d < 1024; d <<= 1) {
        int v = (tid >= d) ? sh[tid - d] : 0;
        __syncthreads();
        sh[tid] += v;
        __syncthreads();
    }
    int run = (tid == 0) ? 0 : sh[tid - 1];
    for (int i = start; i < end; i++) {
        off[i] = run;
        run += cnt[i];
    }
    if (tid == 1023) off[n] = sh[1023];
}

// ---------------- CSR fill ----------------
__global__ void fill_kernel(const int* __restrict__ node_idx, const int* __restrict__ edge_idx,
                            const int* __restrict__ eoff, const int* __restrict__ noff,
                            int* __restrict__ ecur, int* __restrict__ ncur,
                            int* __restrict__ eadj, int* __restrict__ nadj, int nnz) {
    int t = blockIdx.x * blockDim.x + threadIdx.x;
    if (t < nnz) {
        int nd = node_idx[t];
        int eg = edge_idx[t];
        int p = atomicAdd(&ecur[eg], 1);
        eadj[eoff[eg] + p] = nd;
        int q = atomicAdd(&ncur[nd], 1);
        nadj[noff[nd] + q] = eg;
    }
}

// ---------------- pass1: fp16 gather -> fp32 accum -> fp16 out (edge rows) ----------------
template <int VEC>
__global__ void agg_p1(const __half* __restrict__ src, const int* __restrict__ adj,
                       const int* __restrict__ off, __half* __restrict__ out, int rows) {
    int warp = (blockIdx.x * blockDim.x + threadIdx.x) >> 5;
    int lane = threadIdx.x & 31;
    if (warp >= rows) return;
    const int C = 32 * VEC;
    int s0 = off[warp];
    int s1 = off[warp + 1];
    int lo = lane * VEC;

    float acc[VEC];
#pragma unroll
    for (int k = 0; k < VEC; k++) acc[k] = 0.0f;

    int j = s0;
    for (; j + 4 <= s1; j += 4) {
        int nb0 = adj[j + 0], nb1 = adj[j + 1], nb2 = adj[j + 2], nb3 = adj[j + 3];
        const __half2* p0 = reinterpret_cast<const __half2*>(src + (size_t)nb0 * C + lo);
        const __half2* p1 = reinterpret_cast<const __half2*>(src + (size_t)nb1 * C + lo);
        const __half2* p2 = reinterpret_cast<const __half2*>(src + (size_t)nb2 * C + lo);
        const __half2* p3 = reinterpret_cast<const __half2*>(src + (size_t)nb3 * C + lo);
#pragma unroll
        for (int h = 0; h < VEC / 2; h++) {
            float2 a = __half22float2(p0[h]);
            float2 b = __half22float2(p1[h]);
            float2 c = __half22float2(p2[h]);
            float2 d = __half22float2(p3[h]);
            acc[2 * h + 0] += a.x + b.x + c.x + d.x;
            acc[2 * h + 1] += a.y + b.y + c.y + d.y;
        }
    }
    for (; j < s1; j++) {
        int nb = adj[j];
        const __half2* p = reinterpret_cast<const __half2*>(src + (size_t)nb * C + lo);
#pragma unroll
        for (int h = 0; h < VEC / 2; h++) {
            float2 a = __half22float2(p[h]);
            acc[2 * h + 0] += a.x;
            acc[2 * h + 1] += a.y;
        }
    }

    __half2* q = reinterpret_cast<__half2*>(out + (size_t)warp * C + lo);
#pragma unroll
    for (int h = 0; h < VEC / 2; h++)
        q[h] = __floats2half2_rn(acc[2 * h + 0], acc[2 * h + 1]);
}

// ---------------- pass2: fp16 gather (scaled) -> fp32 final with dinv/bias/relu ----------------
template <int VEC>
__global__ void agg_p2(const __half* __restrict__ src, const int* __restrict__ adj,
                       const int* __restrict__ off, const float* __restrict__ sscale,
                       float* __restrict__ out, const float* __restrict__ rscale,
                       const float* __restrict__ bias, int rows) {
    int warp = (blockIdx.x * blockDim.x + threadIdx.x) >> 5;
    int lane = threadIdx.x & 31;
    if (warp >= rows) return;
    const int C = 32 * VEC;
    int s0 = off[warp];
    int s1 = off[warp + 1];
    int lo = lane * VEC;

    float acc[VEC];
#pragma unroll
    for (int k = 0; k < VEC; k++) acc[k] = 0.0f;

    int j = s0;
    for (; j + 4 <= s1; j += 4) {
        int nb0 = adj[j + 0], nb1 = adj[j + 1], nb2 = adj[j + 2], nb3 = adj[j + 3];
        float c0 = sscale[nb0], c1 = sscale[nb1], c2 = sscale[nb2], c3 = sscale[nb3];
        const __half2* p0 = reinterpret_cast<const __half2*>(src + (size_t)nb0 * C + lo);
        const __half2* p1 = reinterpret_cast<const __half2*>(src + (size_t)nb1 * C + lo);
        const __half2* p2 = reinterpret_cast<const __half2*>(src + (size_t)nb2 * C + lo);
        const __half2* p3 = reinterpret_cast<const __half2*>(src + (size_t)nb3 * C + lo);
#pragma unroll
        for (int h = 0; h < VEC / 2; h++) {
            float2 a = __half22float2(p0[h]);
            float2 b = __half22float2(p1[h]);
            float2 c = __half22float2(p2[h]);
            float2 d = __half22float2(p3[h]);
            acc[2 * h + 0] += a.x * c0 + b.x * c1 + c.x * c2 + d.x * c3;
            acc[2 * h + 1] += a.y * c0 + b.y * c1 + c.y * c2 + d.y * c3;
        }
    }
    for (; j < s1; j++) {
        int nb = adj[j];
        float sc = sscale[nb];
        const __half2* p = reinterpret_cast<const __half2*>(src + (size_t)nb * C + lo);
#pragma unroll
        for (int h = 0; h < VEC / 2; h++) {
            float2 a = __half22float2(p[h]);
            acc[2 * h + 0] += a.x * sc;
            acc[2 * h + 1] += a.y * sc;
        }
    }

    float rs = rscale[warp];
#pragma unroll
    for (int k = 0; k < VEC; k++)
        acc[k] = fmaxf(acc[k] * rs + bias[lo + k], 0.0f);

    float* q = out + (size_t)warp * C + lo;
    if (VEC == 4) {
        *reinterpret_cast<float4*>(q) = make_float4(acc[0], acc[1], acc[2], acc[3]);
    } else {
        *reinterpret_cast<float2*>(q) = make_float2(acc[0], acc[1]);
    }
}

// ---------------- fp16 tensor-core GEMM (m16n8k16, fp32 accumulate) ----------------
__device__ __forceinline__ void mma_f16(float* c, const uint32_t* a, const uint32_t* b) {
    asm("mma.sync.aligned.m16n8k16.row.col.f32.f16.f16.f32 "
        "{%0,%1,%2,%3}, {%4,%5,%6,%7}, {%8,%9}, {%0,%1,%2,%3};"
        : "+f"(c[0]), "+f"(c[1]), "+f"(c[2]), "+f"(c[3])
        : "r"(a[0]), "r"(a[1]), "r"(a[2]), "r"(a[3]), "r"(b[0]), "r"(b[1]));
}

// C[M,N] = A[M,K] @ B[K,N] (+bias fp32 path). BM=128, BN=64, BK=32, 256 threads (8 warps 4x2).
// A smem [m][k] fp16 stride 40 halves (conflict-free frag loads: bank = gid*20+tg).
// B smem stored transposed [n][k] fp16 stride 34 halves (contiguous half2 frag loads).
// Inputs converted fp32->fp16 at smem store; accumulate fp32.
template <bool HALF_OUT>
__global__ void __launch_bounds__(256)
f16_gemm(const float* __restrict__ A, const float* __restrict__ B,
         void* __restrict__ Cv, int M, int N, int K,
         const float* __restrict__ bias) {
    const int BM = 128, BN = 64, BK = 32;
    const int ASH = BK + 8;    // 40 halves (80B) row stride
    const int BSH = BK + 2;    // 34 halves (68B) row stride
    __shared__ __half Ah[BM][ASH];
    __shared__ __half Bh[BN][BSH];

    int tid = threadIdx.x;
    int wid = tid >> 5;
    int lane = tid & 31;
    int gid = lane >> 2;       // 0..7
    int tg = lane & 3;         // 0..3
    int warp_m = wid >> 1;     // 0..3
    int warp_n = wid & 1;      // 0..1
    int mb = warp_m * 32;
    int nb = warp_n * 32;

    int rowBase = blockIdx.x * BM;
    int colBase = blockIdx.y * BN;

    float acc[2][4][4];
#pragma unroll
    for (int t = 0; t < 2; t++)
#pragma unroll
        for (int u = 0; u < 4; u++)
#pragma unroll
            for (int k = 0; k < 4; k++) acc[t][u][k] = 0.0f;

    for (int k0 = 0; k0 < K; k0 += BK) {
        // A tile: BM x BK. 4096 elems, 4 float4/thread -> fp16 stores.
#pragma unroll
        for (int it = 0; it < 4; it++) {
            int idx = tid * 4 + it * 1024;
            int r = idx / BK;
            int c = idx % BK;
            int gr = rowBase + r;
            float4 v = make_float4(0.f, 0.f, 0.f, 0.f);
            if (gr < M)
                v = *reinterpret_cast<const float4*>(A + (size_t)gr * K + k0 + c);
            *reinterpret_cast<__half2*>(&Ah[r][c])     = __floats2half2_rn(v.x, v.y);
            *reinterpret_cast<__half2*>(&Ah[r][c + 2]) = __floats2half2_rn(v.z, v.w);
        }
        // B tile: BK x BN, transposed into Bh[n][k]. 2048 elems, 2 float4/thread.
#pragma unroll
        for (int it = 0; it < 2; it++) {
            int idx = tid * 4 + it * 1024;
            int r = idx / BN;       // k within tile
            int c = idx % BN;       // n within tile
            float4 v = *reinterpret_cast<const float4*>(B + (size_t)(k0 + r) * N + colBase + c);
            Bh[c + 0][r] = __float2half(v.x);
            Bh[c + 1][r] = __float2half(v.y);
            Bh[c + 2][r] = __float2half(v.z);
            Bh[c + 3][r] = __float2half(v.w);
        }
        __syncthreads();

#pragma unroll
        for (int ks = 0; ks < 2; ks++) {
            int k = ks * 16;
            int kk = k + tg * 2;
            uint32_t af[2][4];
#pragma unroll
            for (int t = 0; t < 2; t++) {
                int m = mb + t * 16 + gid;
                af[t][0] = *reinterpret_cast<const uint32_t*>(&Ah[m][kk]);
                af[t][1] = *reinterpret_cast<const uint32_t*>(&Ah[m + 8][kk]);
                af[t][2] = *reinterpret_cast<const uint32_t*>(&Ah[m][kk + 8]);
                af[t][3] = *reinterpret_cast<const uint32_t*>(&Ah[m + 8][kk + 8]);
            }
            uint32_t bf[4][2];
#pragma unroll
            for (int u = 0; u < 4; u++) {
                int n = nb + u * 8 + gid;
                bf[u][0] = *reinterpret_cast<const uint32_t*>(&Bh[n][kk]);
                bf[u][1] = *reinterpret_cast<const uint32_t*>(&Bh[n][kk + 8]);
            }
#pragma unroll
            for (int t = 0; t < 2; t++)
#pragma unroll
                for (int u = 0; u < 4; u++)
                    mma_f16(acc[t][u], af[t], bf[u]);
        }
        __syncthreads();
    }

#pragma unroll
    for (int t = 0; t < 2; t++) {
#pragma unroll
        for (int u = 0; u < 4; u++) {
            int row = rowBase + mb + t * 16 + gid;
            int col = colBase + nb + u * 8 + tg * 2;
            if (HALF_OUT) {
                __half* C = (__half*)Cv;
                if (row < M)
                    *reinterpret_cast<__half2*>(C + (size_t)row * N + col) =
                        __floats2half2_rn(acc[t][u][0], acc[t][u][1]);
                if (row + 8 < M)
                    *reinterpret_cast<__half2*>(C + (size_t)(row + 8) * N + col) =
                        __floats2half2_rn(acc[t][u][2], acc[t][u][3]);
            } else {
                float* C = (float*)Cv;
                float b0 = 0.f, b1 = 0.f;
                if (bias) { b0 = bias[col]; b1 = bias[col + 1]; }
                if (row < M) {
                    float2 v = make_float2(acc[t][u][0] + b0, acc[t][u][1] + b1);
                    *reinterpret_cast<float2*>(C + (size_t)row * N + col) = v;
                }
                if (row + 8 < M) {
                    float2 v = make_float2(acc[t][u][2] + b0, acc[t][u][3] + b1);
                    *reinterpret_cast<float2*>(C + (size_t)(row + 8) * N + col) = v;
                }
            }
        }
    }
}

// ---------------- launch ----------------
extern "C" void kernel_launch(void* const* d_in, const int* in_sizes, int n_in,
                              void* d_out, int out_size) {
    const float* x    = (const float*)d_in[0];
    const int*   hidx = (const int*)d_in[1];   // int32 on device (JAX x64 disabled)
    const float* W1   = (const float*)d_in[2];
    const float* b1   = (const float*)d_in[3];
    const float* W2   = (const float*)d_in[4];
    const float* b2   = (const float*)d_in[5];
    const float* Wp   = (const float*)d_in[6];
    const float* bp   = (const float*)d_in[7];

    int nnz = in_sizes[1] / 2;
    const int* node_idx = hidx;
    const int* edge_idx = hidx + nnz;

    // output layout: (z [N,64], features_1 [N,128], features_2 [N,64])
    float* z  = (float*)d_out;
    float* f1 = z  + (size_t)N_NODES * OUT_C;
    float* f2 = f1 + (size_t)N_NODES * HID_C;

    __half *p_h0h, *p_h1h, *p_mh;
    float *p_dinv, *p_binv;
    int *p_cnt, *p_eoff, *p_noff, *p_eadj, *p_nadj;
    cudaGetSymbolAddress((void**)&p_h0h,  g_h0h);
    cudaGetSymbolAddress((void**)&p_h1h,  g_h1h);
    cudaGetSymbolAddress((void**)&p_mh,   g_mh);
    cudaGetSymbolAddress((void**)&p_dinv, g_dinv);
    cudaGetSymbolAddress((void**)&p_binv, g_binv);
    cudaGetSymbolAddress((void**)&p_cnt,  g_cnt);
    cudaGetSymbolAddress((void**)&p_eoff, g_eoff);
    cudaGetSymbolAddress((void**)&p_noff, g_noff);
    cudaGetSymbolAddress((void**)&p_eadj, g_eadj);
    cudaGetSymbolAddress((void**)&p_nadj, g_nadj);

    int* p_ecnt = p_cnt;
    int* p_ncnt = p_cnt + N_EDGES;
    int* p_ecur = p_cnt + 2 * N_EDGES;
    int* p_ncur = p_cnt + 3 * N_EDGES;

    static cudaStream_t s_csr = nullptr;
    static cudaEvent_t ev_fork = nullptr, ev_join = nullptr;
    if (!s_csr) {
        cudaStreamCreateWithFlags(&s_csr, cudaStreamNonBlocking);
        cudaEventCreateWithFlags(&ev_fork, cudaEventDisableTiming);
        cudaEventCreateWithFlags(&ev_join, cudaEventDisableTiming);
    }

    int agg_blocks = (N_EDGES * 32 + 255) / 256;
    dim3 ggrid((N_NODES + 127) / 128, 1);

    // ---- fork: CSR build on side stream, gemm1 on main stream ----
    cudaEventRecord(ev_fork, 0);
    cudaStreamWaitEvent(s_csr, ev_fork, 0);

    cudaMemsetAsync(p_cnt, 0, 4 * N_EDGES * sizeof(int), s_csr);
    hist_kernel<<<(nnz + 255) / 256, 256, 0, s_csr>>>(node_idx, edge_idx, p_ncnt, p_ecnt, nnz);
    scan_kernel<<<2, 1024, 0, s_csr>>>(p_ecnt, p_eoff, p_ncnt, p_noff, p_binv, p_dinv, N_EDGES);
    fill_kernel<<<(nnz + 255) / 256, 256, 0, s_csr>>>(node_idx, edge_idx, p_eoff, p_noff,
                                                      p_ecur, p_ncur, p_eadj, p_nadj, nnz);
    cudaEventRecord(ev_join, s_csr);

    // ---- layer 1: h0 = x @ W1 (fp16 out) ---- (M=50000, N=128, K=256)
    {
        dim3 grid((N_NODES + 127) / 128, HID_C / 64);
        f16_gemm<true><<<grid, 256>>>(x, W1, p_h0h, N_NODES, HID_C, IN_C, nullptr);
    }

    // ---- join: aggregation needs both gemm1 and the CSR ----
    cudaStreamWaitEvent(0, ev_join, 0);

    agg_p1<4><<<agg_blocks, 256>>>(p_h0h, p_eadj, p_eoff, p_mh, N_EDGES);
    agg_p2<4><<<agg_blocks, 256>>>(p_mh, p_nadj, p_noff, p_binv, f1, p_dinv, b1, N_NODES);

    // ---- layer 2: h1 = f1 @ W2 (fp16 out) ---- (M=50000, N=64, K=128)
    f16_gemm<true><<<ggrid, 256>>>(f1, W2, p_h1h, N_NODES, OUT_C, HID_C, nullptr);
    agg_p1<2><<<agg_blocks, 256>>>(p_h1h, p_eadj, p_eoff, p_mh, N_EDGES);
    agg_p2<2><<<agg_blocks, 256>>>(p_mh, p_nadj, p_noff, p_binv, f2, p_dinv, b2, N_NODES);

    // ---- projection: z = f2 @ Wp + bp (fp32 out) ---- (M=50000, N=64, K=64)
    f16_gemm<false><<<ggrid, 256>>>(f2, Wp, z, N_NODES, OUT_C, OUT_C, bp);
}